// round 9
// baseline (speedup 1.0000x reference)
#include <cuda_runtime.h>
#include <cuda_bf16.h>
#include <cstddef>

// Problem constants
#define Hh   512
#define INPS 2048
#define FS   1536
#define Bb   128
#define Tt   64
#define MROWS (Bb * Tt)          // 8192

// Persistent-recurrence tiling
#define NC   16                  // hidden cols per CTA
#define BBB  32                  // batch rows per CTA
#define NBLK 128                 // total CTAs (32 col-chunks x 4 batch-chunks)
#define STEP_THREADS 256

// Scratch for precomputed projections (device statics: allocation-free)
__device__ float g_gi[(size_t)MROWS * (3 * Hh)];   // [B*T, 1536]
__device__ float g_gf[(size_t)MROWS * (2 * Hh)];   // [B*T, 1024]
__device__ unsigned int g_bar;                      // grid-barrier counter (monotone)

// ---------------------------------------------------------------------------
// TF32 tensor-core GEMM, double-buffered: C[M,N] = A[M,K]*W[N,K]^T + bias[N]
// CTA tile 128x128, BK=16, 8 warps (2x4), warp tile 64x32 = 4x4 m16n8k8.
// Two smem buffers; next tile's LDGs prefetched into registers while MMAs
// consume the current buffer. Pad-4 rows (stride 20 words) keeps fragment
// LDS conflict-free.
// ---------------------------------------------------------------------------
#define GS 20   // 16 + 4 pad (uint32 words per smem row)
#define BUFW (128 * GS)

__device__ __forceinline__ unsigned int f2tf32(float x) {
    unsigned int u;
    asm("cvt.rna.tf32.f32 %0, %1;" : "=r"(u) : "f"(x));
    return u;
}

__global__ __launch_bounds__(256, 2)
void tf32_gemm_bias_kernel(const float* __restrict__ A,
                           const float* __restrict__ W,
                           const float* __restrict__ bias,
                           float* __restrict__ C,
                           int M, int N, int K)
{
    __shared__ unsigned int As[2 * BUFW];
    __shared__ unsigned int Ws[2 * BUFW];

    const int tid  = threadIdx.x;
    const int lane = tid & 31;
    const int warp = tid >> 5;          // 0..7
    const int gid  = lane >> 2;         // 0..7
    const int tig  = lane & 3;          // 0..3
    const int wm   = warp >> 2;         // 0..1 -> M offset wm*64
    const int wn   = warp & 3;          // 0..3 -> N offset wn*32

    const int bm = blockIdx.y;          // M/128
    const int bn = blockIdx.x;          // N/128

    // Staging map: idx = tid + i*256 (i<2); row = idx>>2, c4 = idx&3
    const int srow0 = tid >> 2;         // i=0 row (0..63)
    const int sc4   = tid & 3;
    // i=1: row = srow0 + 64, same c4

    const float* Ablk = A + (size_t)bm * 128 * K;
    const float* Wblk = W + (size_t)bn * 128 * K;

    float acc[4][4][4];
#pragma unroll
    for (int i = 0; i < 4; i++)
#pragma unroll
        for (int j = 0; j < 4; j++)
#pragma unroll
            for (int f = 0; f < 4; f++) acc[i][j][f] = 0.0f;

    const int KT = K >> 4;              // BK=16 tiles
    float4 aReg[2], wReg[2];

    // Prologue: load tile 0 into regs, cvt+STS into buffer 0
#pragma unroll
    for (int i = 0; i < 2; i++) {
        int row = srow0 + i * 64;
        aReg[i] = *(const float4*)(Ablk + (size_t)row * K + sc4 * 4);
        wReg[i] = *(const float4*)(Wblk + (size_t)row * K + sc4 * 4);
    }
#pragma unroll
    for (int i = 0; i < 2; i++) {
        int row = srow0 + i * 64;
        unsigned int* da = &As[row * GS + sc4 * 4];
        da[0] = f2tf32(aReg[i].x); da[1] = f2tf32(aReg[i].y);
        da[2] = f2tf32(aReg[i].z); da[3] = f2tf32(aReg[i].w);
        unsigned int* dw = &Ws[row * GS + sc4 * 4];
        dw[0] = f2tf32(wReg[i].x); dw[1] = f2tf32(wReg[i].y);
        dw[2] = f2tf32(wReg[i].z); dw[3] = f2tf32(wReg[i].w);
    }
    __syncthreads();

    for (int kt = 0; kt < KT; kt++) {
        const int buf = (kt & 1) * BUFW;

        // Prefetch next tile into registers (overlaps with MMA below)
        if (kt + 1 < KT) {
            const int k0 = (kt + 1) << 4;
#pragma unroll
            for (int i = 0; i < 2; i++) {
                int row = srow0 + i * 64;
                aReg[i] = *(const float4*)(Ablk + (size_t)row * K + k0 + sc4 * 4);
                wReg[i] = *(const float4*)(Wblk + (size_t)row * K + k0 + sc4 * 4);
            }
        }

        // MMA over current buffer (2 kk-steps of 8)
#pragma unroll
        for (int kk = 0; kk < 16; kk += 8) {
            unsigned int af[4][4];
#pragma unroll
            for (int mt = 0; mt < 4; mt++) {
                int r0 = wm * 64 + mt * 16 + gid;
                const unsigned int* p = &As[buf + r0 * GS + kk + tig];
                af[mt][0] = p[0];
                af[mt][1] = p[8 * GS];
                af[mt][2] = p[4];
                af[mt][3] = p[8 * GS + 4];
            }
            unsigned int bf[4][2];
#pragma unroll
            for (int nt = 0; nt < 4; nt++) {
                int n0 = wn * 32 + nt * 8 + gid;
                const unsigned int* p = &Ws[buf + n0 * GS + kk + tig];
                bf[nt][0] = p[0];
                bf[nt][1] = p[4];
            }
#pragma unroll
            for (int mt = 0; mt < 4; mt++)
#pragma unroll
                for (int nt = 0; nt < 4; nt++) {
                    asm volatile(
                        "mma.sync.aligned.m16n8k8.row.col.f32.tf32.tf32.f32 "
                        "{%0,%1,%2,%3}, {%4,%5,%6,%7}, {%8,%9}, {%0,%1,%2,%3};\n"
                        : "+f"(acc[mt][nt][0]), "+f"(acc[mt][nt][1]),
                          "+f"(acc[mt][nt][2]), "+f"(acc[mt][nt][3])
                        : "r"(af[mt][0]), "r"(af[mt][1]),
                          "r"(af[mt][2]), "r"(af[mt][3]),
                          "r"(bf[nt][0]), "r"(bf[nt][1]));
                }
        }

        // Stage prefetched tile into the other buffer
        if (kt + 1 < KT) {
            const int obuf = ((kt + 1) & 1) * BUFW;
#pragma unroll
            for (int i = 0; i < 2; i++) {
                int row = srow0 + i * 64;
                unsigned int* da = &As[obuf + row * GS + sc4 * 4];
                da[0] = f2tf32(aReg[i].x); da[1] = f2tf32(aReg[i].y);
                da[2] = f2tf32(aReg[i].z); da[3] = f2tf32(aReg[i].w);
                unsigned int* dw = &Ws[obuf + row * GS + sc4 * 4];
                dw[0] = f2tf32(wReg[i].x); dw[1] = f2tf32(wReg[i].y);
                dw[2] = f2tf32(wReg[i].z); dw[3] = f2tf32(wReg[i].w);
            }
        }
        __syncthreads();
    }

    // Epilogue: bias + store
#pragma unroll
    for (int mt = 0; mt < 4; mt++) {
        const int row = bm * 128 + wm * 64 + mt * 16 + gid;
#pragma unroll
        for (int nt = 0; nt < 4; nt++) {
            const int col = bn * 128 + wn * 32 + nt * 8 + tig * 2;
            const float b0 = bias[col], b1 = bias[col + 1];
            float2 v0 = make_float2(acc[mt][nt][0] + b0, acc[mt][nt][1] + b1);
            float2 v1 = make_float2(acc[mt][nt][2] + b0, acc[mt][nt][3] + b1);
            *(float2*)(C + (size_t)row * N + col)       = v0;
            *(float2*)(C + (size_t)(row + 8) * N + col) = v1;
        }
    }
}

// ---------------------------------------------------------------------------
// Persistent GRU recurrence: ONE kernel runs all 64 timesteps.
// 128 CTAs (32 col-chunks x 4 batch-chunks), all co-resident (1/SM at 160KB smem).
// W_hh slice lives in smem for the whole kernel. Software grid barrier per step.
// Gate projections (gi/gf) prefetched at step start -> hidden under FMA loop.
// ---------------------------------------------------------------------------
__global__ __launch_bounds__(STEP_THREADS, 1)
void gru_persistent_kernel(const float* __restrict__ gi,     // [B*T, 1536]
                           const float* __restrict__ gf,     // [B*T, 1024]
                           const float* __restrict__ W_hh,   // [1536, 512]
                           const float* __restrict__ b_hh,   // [1536]
                           float* __restrict__ out)          // eo [B,T,H] then hT [B,H]
{
    extern __shared__ float sm[];
    float* W_sm = sm;                        // [3][512][NC]  (k-major rows of NC cols)
    float* h_sm = sm + 3 * Hh * NC;          // [BBB][512]

    const int tid = threadIdx.x;
    const int c   = tid & (NC - 1);          // 0..15
    const int bg  = tid >> 4;                // 0..15
    const int colBase = blockIdx.x * NC;     // 0..496
    const int bBase   = blockIdx.y * BBB;    // 0..96
    const int n = colBase + c;

    // ---- One-time: stage W_hh slice (3 gates x NC cols x 512 k) into smem ----
    for (int i = tid; i < 3 * NC * (Hh / 4); i += STEP_THREADS) {
        int r  = i >> 7;          // row 0..(3*NC-1): g*NC + cc
        int kq = i & 127;         // float4 index over k
        int g  = r / NC;
        int cc = r - g * NC;
        float4 v = *(const float4*)(W_hh + (size_t)(g * Hh + colBase + cc) * Hh + kq * 4);
        int k = kq * 4;
        W_sm[((g * Hh) + k + 0) * NC + cc] = v.x;
        W_sm[((g * Hh) + k + 1) * NC + cc] = v.y;
        W_sm[((g * Hh) + k + 2) * NC + cc] = v.z;
        W_sm[((g * Hh) + k + 3) * NC + cc] = v.w;
    }

    const float bhr = b_hh[n];
    const float bhi = b_hh[Hh + n];
    const float bhn = b_hh[2 * Hh + n];

    for (int t = 0; t < Tt; t++) {
        // ---- Prefetch gate projections for this step (independent of h) ----
        float gir[2][3], gfr[2][2];
#pragma unroll
        for (int j = 0; j < 2; j++) {
            const int b = bBase + bg * 2 + j;
            const size_t gib = ((size_t)b * Tt + t) * (3 * Hh);
            const size_t gfb = ((size_t)b * Tt + t) * (2 * Hh);
            gir[j][0] = gi[gib + n];
            gir[j][1] = gi[gib + Hh + n];
            gir[j][2] = gi[gib + 2 * Hh + n];
            gfr[j][0] = gf[gfb + n];
            gfr[j][1] = gf[gfb + Hh + n];
        }

        // ---- Stage h_{t-1}[bBase..bBase+31, :] into smem ----
        if (t == 0) {
            float4 z = make_float4(0.f, 0.f, 0.f, 0.f);
            for (int i = tid; i < BBB * (Hh / 4); i += STEP_THREADS)
                *(float4*)(h_sm + i * 4) = z;
        } else {
            for (int i = tid; i < BBB * (Hh / 4); i += STEP_THREADS) {
                int bl = i >> 7;           // local batch
                int kq = i & 127;
                float4 v = *(const float4*)(out +
                    ((size_t)(bBase + bl) * Tt + (t - 1)) * Hh + kq * 4);
                *(float4*)(h_sm + bl * Hh + kq * 4) = v;
            }
        }
        __syncthreads();

        // ---- gh = h_{t-1} @ W_hh^T for this (batch,col) tile ----
        float a00 = 0.f, a01 = 0.f;
        float a10 = 0.f, a11 = 0.f;
        float a20 = 0.f, a21 = 0.f;
        const float* h0p = h_sm + (bg * 2 + 0) * Hh;
        const float* h1p = h_sm + (bg * 2 + 1) * Hh;
        const float* w0p = W_sm + (0 * Hh) * NC + c;
        const float* w1p = W_sm + (1 * Hh) * NC + c;
        const float* w2p = W_sm + (2 * Hh) * NC + c;
#pragma unroll 8
        for (int k = 0; k < Hh; k++) {
            float h0 = h0p[k];
            float h1 = h1p[k];
            float w0 = w0p[k * NC];
            float w1 = w1p[k * NC];
            float w2 = w2p[k * NC];
            a00 = fmaf(w0, h0, a00);  a01 = fmaf(w0, h1, a01);
            a10 = fmaf(w1, h0, a10);  a11 = fmaf(w1, h1, a11);
            a20 = fmaf(w2, h0, a20);  a21 = fmaf(w2, h1, a21);
        }

        // ---- Gates + state update ----
#pragma unroll
        for (int j = 0; j < 2; j++) {
            const int b = bBase + bg * 2 + j;

            float ghr = (j ? a01 : a00) + bhr;
            float ghi = (j ? a11 : a10) + bhi;
            float ghn = (j ? a21 : a20) + bhn;

            float xr = gir[j][0] + ghr + gfr[j][0];
            float xi = gir[j][1] + ghi + gfr[j][1];
            float resetgate = 1.0f / (1.0f + expf(-xr));
            float inputgate = 1.0f / (1.0f + expf(-xi));
            float newgate   = tanhf(gir[j][2] + resetgate * ghn);

            float hprev = h_sm[(bg * 2 + j) * Hh + n];
            float hy = newgate + inputgate * (hprev - newgate);

            out[((size_t)b * Tt + t) * Hh + n] = hy;
            if (t == Tt - 1)
                out[(size_t)Bb * Tt * Hh + (size_t)b * Hh + n] = hy;
        }

        // ---- Grid-wide barrier (all 128 CTAs co-resident) ----
        __threadfence();
        __syncthreads();
        if (tid == 0) {
            unsigned int old  = atomicAdd(&g_bar, 1u);
            unsigned int need = (old / NBLK + 1u) * NBLK;
            while (true) {
                unsigned int cur;
                asm volatile("ld.acquire.gpu.u32 %0, [%1];"
                             : "=r"(cur) : "l"(&g_bar));
                if (cur >= need) break;
            }
            __threadfence();
        }
        __syncthreads();
    }
}

// ---------------------------------------------------------------------------
// Launch
// ---------------------------------------------------------------------------
extern "C" void kernel_launch(void* const* d_in, const int* in_sizes, int n_in,
                              void* d_out, int out_size)
{
    const float* feat0 = (const float*)d_in[0];   // [B,T,FS]
    const float* feat1 = (const float*)d_in[1];   // [B,T,IN]
    const float* W_ih  = (const float*)d_in[2];   // [3H, IN]
    const float* b_ih  = (const float*)d_in[3];   // [3H]
    const float* W_hh  = (const float*)d_in[4];   // [3H, H]
    const float* b_hh  = (const float*)d_in[5];   // [3H]
    const float* W_fh  = (const float*)d_in[6];   // [2H, FS]
    const float* b_fh  = (const float*)d_in[7];   // [2H]
    float* out = (float*)d_out;

    float *gi_ptr, *gf_ptr;
    cudaGetSymbolAddress((void**)&gi_ptr, g_gi);
    cudaGetSymbolAddress((void**)&gf_ptr, g_gf);

    // gi = feat1 @ W_ih^T + b_ih : M=8192, N=1536, K=2048  (tf32 tensor path)
    {
        dim3 grid((3 * Hh) / 128, MROWS / 128);   // (12, 64)
        tf32_gemm_bias_kernel<<<grid, 256>>>(feat1, W_ih, b_ih, gi_ptr,
                                             MROWS, 3 * Hh, INPS);
    }
    // gf = feat0 @ W_fh^T + b_fh : M=8192, N=1024, K=1536  (tf32 tensor path)
    {
        dim3 grid((2 * Hh) / 128, MROWS / 128);   // (8, 64)
        tf32_gemm_bias_kernel<<<grid, 256>>>(feat0, W_fh, b_fh, gf_ptr,
                                             MROWS, 2 * Hh, FS);
    }
    // Recurrence: single persistent kernel, 64 steps internally
    {
        const int smem_bytes = (3 * Hh * NC + BBB * Hh) * (int)sizeof(float); // 163840
        cudaFuncSetAttribute(gru_persistent_kernel,
                             cudaFuncAttributeMaxDynamicSharedMemorySize, smem_bytes);
        dim3 grid(Hh / NC, Bb / BBB);   // (32, 4) = 128 CTAs
        gru_persistent_kernel<<<grid, STEP_THREADS, smem_bytes>>>(
            gi_ptr, gf_ptr, W_hh, b_hh, out);
    }
}

// round 10
// speedup vs baseline: 1.5359x; 1.5359x over previous
#include <cuda_runtime.h>
#include <cuda_bf16.h>
#include <cstddef>

// Problem constants
#define Hh   512
#define INPS 2048
#define FS   1536
#define Bb   128
#define Tt   64
#define MROWS (Bb * Tt)          // 8192

// Persistent-recurrence tiling
#define NC   16                  // hidden cols per CTA (48 gate-cols)
#define BBB  32                  // batch rows per CTA
#define NBLK 128                 // total CTAs (32 col-chunks x 4 batch-chunks)
#define STEP_THREADS 256
#define HS   516                 // h_sm row stride (conflict-free frag LDS)
#define GHS  50                  // gh_sm row stride (48 + 2 pad)

// Scratch for precomputed projections (device statics: allocation-free)
__device__ float g_gi[(size_t)MROWS * (3 * Hh)];   // [B*T, 1536]
__device__ float g_gf[(size_t)MROWS * (2 * Hh)];   // [B*T, 1024]
__device__ unsigned int g_bar;                      // grid-barrier counter (monotone)

__device__ __forceinline__ unsigned int f2tf32(float x) {
    unsigned int u;
    asm("cvt.rna.tf32.f32 %0, %1;" : "=r"(u) : "f"(x));
    return u;
}

// ---------------------------------------------------------------------------
// TF32 tensor-core GEMM (single-buffer BK=32 — the known-best R7 version):
// C[M,N] = A[M,K] * W[N,K]^T + bias[N]
// CTA tile 128x128x32, 8 warps (2x4), warp tile 64x32 = 4x4 m16n8k8 tiles.
// ---------------------------------------------------------------------------
#define GSTRIDE 36   // 32 + 4 pad (uint32 words per smem row)

__global__ __launch_bounds__(256, 2)
void tf32_gemm_bias_kernel(const float* __restrict__ A,
                           const float* __restrict__ W,
                           const float* __restrict__ bias,
                           float* __restrict__ C,
                           int M, int N, int K)
{
    __shared__ unsigned int As[128 * GSTRIDE];
    __shared__ unsigned int Ws[128 * GSTRIDE];

    const int tid  = threadIdx.x;
    const int lane = tid & 31;
    const int warp = tid >> 5;          // 0..7
    const int gid  = lane >> 2;         // 0..7
    const int tig  = lane & 3;          // 0..3
    const int wm   = warp >> 2;         // 0..1 -> M offset wm*64
    const int wn   = warp & 3;          // 0..3 -> N offset wn*32

    const int bm = blockIdx.y;          // M/128
    const int bn = blockIdx.x;          // N/128

    const float* Ablk = A + (size_t)bm * 128 * K;
    const float* Wblk = W + (size_t)bn * 128 * K;

    float acc[4][4][4];                 // [m-tile][n-tile][frag]
#pragma unroll
    for (int i = 0; i < 4; i++)
#pragma unroll
        for (int j = 0; j < 4; j++)
#pragma unroll
            for (int f = 0; f < 4; f++) acc[i][j][f] = 0.0f;

    for (int k0 = 0; k0 < K; k0 += 32) {
#pragma unroll
        for (int i = 0; i < 4; i++) {
            int idx = tid + i * 256;            // 0..1023
            int row = idx >> 3;                 // /8
            int c4  = idx & 7;
            float4 v = *(const float4*)(Ablk + (size_t)row * K + k0 + c4 * 4);
            unsigned int* dst = &As[row * GSTRIDE + c4 * 4];
            dst[0] = f2tf32(v.x); dst[1] = f2tf32(v.y);
            dst[2] = f2tf32(v.z); dst[3] = f2tf32(v.w);
        }
#pragma unroll
        for (int i = 0; i < 4; i++) {
            int idx = tid + i * 256;
            int row = idx >> 3;
            int c4  = idx & 7;
            float4 v = *(const float4*)(Wblk + (size_t)row * K + k0 + c4 * 4);
            unsigned int* dst = &Ws[row * GSTRIDE + c4 * 4];
            dst[0] = f2tf32(v.x); dst[1] = f2tf32(v.y);
            dst[2] = f2tf32(v.z); dst[3] = f2tf32(v.w);
        }
        __syncthreads();

#pragma unroll
        for (int kk = 0; kk < 32; kk += 8) {
            unsigned int af[4][4];
#pragma unroll
            for (int mt = 0; mt < 4; mt++) {
                int r0 = wm * 64 + mt * 16 + gid;
                const unsigned int* p = &As[r0 * GSTRIDE + kk + tig];
                af[mt][0] = p[0];
                af[mt][1] = p[8 * GSTRIDE];
                af[mt][2] = p[4];
                af[mt][3] = p[8 * GSTRIDE + 4];
            }
            unsigned int bf[4][2];
#pragma unroll
            for (int nt = 0; nt < 4; nt++) {
                int n0 = wn * 32 + nt * 8 + gid;
                const unsigned int* p = &Ws[n0 * GSTRIDE + kk + tig];
                bf[nt][0] = p[0];
                bf[nt][1] = p[4];
            }
#pragma unroll
            for (int mt = 0; mt < 4; mt++)
#pragma unroll
                for (int nt = 0; nt < 4; nt++) {
                    asm volatile(
                        "mma.sync.aligned.m16n8k8.row.col.f32.tf32.tf32.f32 "
                        "{%0,%1,%2,%3}, {%4,%5,%6,%7}, {%8,%9}, {%0,%1,%2,%3};\n"
                        : "+f"(acc[mt][nt][0]), "+f"(acc[mt][nt][1]),
                          "+f"(acc[mt][nt][2]), "+f"(acc[mt][nt][3])
                        : "r"(af[mt][0]), "r"(af[mt][1]),
                          "r"(af[mt][2]), "r"(af[mt][3]),
                          "r"(bf[nt][0]), "r"(bf[nt][1]));
                }
        }
        __syncthreads();
    }

#pragma unroll
    for (int mt = 0; mt < 4; mt++) {
        const int row = bm * 128 + wm * 64 + mt * 16 + gid;
#pragma unroll
        for (int nt = 0; nt < 4; nt++) {
            const int col = bn * 128 + wn * 32 + nt * 8 + tig * 2;
            const float b0 = bias[col], b1 = bias[col + 1];
            float2 v0 = make_float2(acc[mt][nt][0] + b0, acc[mt][nt][1] + b1);
            float2 v1 = make_float2(acc[mt][nt][2] + b0, acc[mt][nt][3] + b1);
            *(float2*)(C + (size_t)row * N + col)       = v0;
            *(float2*)(C + (size_t)(row + 8) * N + col) = v1;
        }
    }
}

// ---------------------------------------------------------------------------
// Persistent GRU recurrence with TENSOR-CORE gh GEMM.
// 128 CTAs (32 col-chunks x 4 batch-chunks), 1/SM, 256 threads.
// Per CTA: gh = h[32,512] @ Whh_slice[48,512]^T, W held in REGISTERS as
// tf32 B-fragments (warps 0..5, 128 regs each); h staged to smem as tf32.
// gh -> smem -> gating (all 256 threads) -> out; software grid barrier.
// ---------------------------------------------------------------------------
__global__ __launch_bounds__(STEP_THREADS, 1)
void gru_persistent_kernel(const float* __restrict__ gi,     // [B*T, 1536]
                           const float* __restrict__ gf,     // [B*T, 1024]
                           const float* __restrict__ W_hh,   // [1536, 512]
                           const float* __restrict__ b_hh,   // [1536]
                           float* __restrict__ out)          // eo [B,T,H] then hT [B,H]
{
    extern __shared__ unsigned int smu[];
    unsigned int* h_sm  = smu;                         // [32][HS] tf32 bits
    float*        gh_sm = (float*)(smu + BBB * HS);    // [32][GHS]

    const int tid  = threadIdx.x;
    const int lane = tid & 31;
    const int warp = tid >> 5;            // 0..7
    const int gid  = lane >> 2;           // 0..7
    const int tig  = lane & 3;            // 0..3
    const int c    = tid & (NC - 1);      // 0..15
    const int bg   = tid >> 4;            // 0..15
    const int colBase = blockIdx.x * NC;  // 0..496
    const int bBase   = blockIdx.y * BBB; // 0..96
    const int n = colBase + c;

    // ---- One-time: W_hh slice -> registers as tf32 B-fragments ----
    // Warp w (<6): gate g=w>>1, col block (w&1)*8. B frag col = colBase + (w&1)*8 + gid.
    unsigned int wb0[64], wb1[64];
    if (warp < 6) {
        const float* Wg = W_hh +
            ((size_t)((warp >> 1) * Hh + colBase + (warp & 1) * 8 + gid)) * Hh;
#pragma unroll
        for (int ks = 0; ks < 64; ks++) {
            wb0[ks] = f2tf32(Wg[ks * 8 + tig]);
            wb1[ks] = f2tf32(Wg[ks * 8 + tig + 4]);
        }
    }

    const float bhr = b_hh[n];
    const float bhi = b_hh[Hh + n];
    const float bhn = b_hh[2 * Hh + n];

    for (int t = 0; t < Tt; t++) {
        // ---- Prefetch gate projections + hprev for this thread's outputs ----
        float gir[2][3], gfr[2][2], hpr[2];
#pragma unroll
        for (int j = 0; j < 2; j++) {
            const int b = bBase + bg * 2 + j;
            const size_t gib = ((size_t)b * Tt + t) * (3 * Hh);
            const size_t gfb = ((size_t)b * Tt + t) * (2 * Hh);
            gir[j][0] = gi[gib + n];
            gir[j][1] = gi[gib + Hh + n];
            gir[j][2] = gi[gib + 2 * Hh + n];
            gfr[j][0] = gf[gfb + n];
            gfr[j][1] = gf[gfb + Hh + n];
            hpr[j] = (t > 0) ? out[((size_t)b * Tt + (t - 1)) * Hh + n] : 0.0f;
        }

        // ---- Stage h_{t-1}[bBase..+31, :] into smem as tf32 ----
        if (t == 0) {
            uint4 z = make_uint4(0u, 0u, 0u, 0u);
            for (int i = tid; i < BBB * (Hh / 4); i += STEP_THREADS) {
                int bl = i >> 7;
                int kq = i & 127;
                *(uint4*)(h_sm + bl * HS + kq * 4) = z;
            }
        } else {
            for (int i = tid; i < BBB * (Hh / 4); i += STEP_THREADS) {
                int bl = i >> 7;
                int kq = i & 127;
                float4 v = *(const float4*)(out +
                    ((size_t)(bBase + bl) * Tt + (t - 1)) * Hh + kq * 4);
                uint4 u;
                u.x = f2tf32(v.x); u.y = f2tf32(v.y);
                u.z = f2tf32(v.z); u.w = f2tf32(v.w);
                *(uint4*)(h_sm + bl * HS + kq * 4) = u;
            }
        }
        __syncthreads();

        // ---- Tensor-core gh: [32,48] = h[32,512] @ Wslice[48,512]^T ----
        if (warp < 6) {
            float acc[2][4];
#pragma unroll
            for (int mt = 0; mt < 2; mt++)
#pragma unroll
                for (int f = 0; f < 4; f++) acc[mt][f] = 0.0f;

#pragma unroll
            for (int ks = 0; ks < 64; ks++) {
                const int kk = ks * 8;
#pragma unroll
                for (int mt = 0; mt < 2; mt++) {
                    const unsigned int* p = h_sm + (mt * 16 + gid) * HS + kk + tig;
                    unsigned int a0 = p[0];
                    unsigned int a1 = p[8 * HS];
                    unsigned int a2 = p[4];
                    unsigned int a3 = p[8 * HS + 4];
                    asm volatile(
                        "mma.sync.aligned.m16n8k8.row.col.f32.tf32.tf32.f32 "
                        "{%0,%1,%2,%3}, {%4,%5,%6,%7}, {%8,%9}, {%0,%1,%2,%3};\n"
                        : "+f"(acc[mt][0]), "+f"(acc[mt][1]),
                          "+f"(acc[mt][2]), "+f"(acc[mt][3])
                        : "r"(a0), "r"(a1), "r"(a2), "r"(a3),
                          "r"(wb0[ks]), "r"(wb1[ks]));
                }
            }
            // Write gh tile: warp covers 48-col range [warp*8, warp*8+8)
#pragma unroll
            for (int mt = 0; mt < 2; mt++) {
                int r = mt * 16 + gid;
                *(float2*)(gh_sm + (size_t)r * GHS + warp * 8 + tig * 2) =
                    make_float2(acc[mt][0], acc[mt][1]);
                *(float2*)(gh_sm + (size_t)(r + 8) * GHS + warp * 8 + tig * 2) =
                    make_float2(acc[mt][2], acc[mt][3]);
            }
        }
        __syncthreads();

        // ---- Gates + state update (all 256 threads) ----
#pragma unroll
        for (int j = 0; j < 2; j++) {
            const int bl = bg * 2 + j;
            const int b  = bBase + bl;

            float ghr = gh_sm[(size_t)bl * GHS + c]            + bhr;
            float ghi = gh_sm[(size_t)bl * GHS + NC + c]       + bhi;
            float ghn = gh_sm[(size_t)bl * GHS + 2 * NC + c]   + bhn;

            float xr = gir[j][0] + ghr + gfr[j][0];
            float xi = gir[j][1] + ghi + gfr[j][1];
            float resetgate = 1.0f / (1.0f + expf(-xr));
            float inputgate = 1.0f / (1.0f + expf(-xi));
            float newgate   = tanhf(gir[j][2] + resetgate * ghn);

            float hy = newgate + inputgate * (hpr[j] - newgate);

            out[((size_t)b * Tt + t) * Hh + n] = hy;
            if (t == Tt - 1)
                out[(size_t)Bb * Tt * Hh + (size_t)b * Hh + n] = hy;
        }

        // ---- Grid-wide barrier (all 128 CTAs co-resident) ----
        __threadfence();
        __syncthreads();
        if (tid == 0) {
            unsigned int old  = atomicAdd(&g_bar, 1u);
            unsigned int need = (old / NBLK + 1u) * NBLK;
            while (true) {
                unsigned int cur;
                asm volatile("ld.acquire.gpu.u32 %0, [%1];"
                             : "=r"(cur) : "l"(&g_bar));
                if (cur >= need) break;
            }
            __threadfence();
        }
        __syncthreads();
    }
}

// ---------------------------------------------------------------------------
// Launch
// ---------------------------------------------------------------------------
extern "C" void kernel_launch(void* const* d_in, const int* in_sizes, int n_in,
                              void* d_out, int out_size)
{
    const float* feat0 = (const float*)d_in[0];   // [B,T,FS]
    const float* feat1 = (const float*)d_in[1];   // [B,T,IN]
    const float* W_ih  = (const float*)d_in[2];   // [3H, IN]
    const float* b_ih  = (const float*)d_in[3];   // [3H]
    const float* W_hh  = (const float*)d_in[4];   // [3H, H]
    const float* b_hh  = (const float*)d_in[5];   // [3H]
    const float* W_fh  = (const float*)d_in[6];   // [2H, FS]
    const float* b_fh  = (const float*)d_in[7];   // [2H]
    float* out = (float*)d_out;

    float *gi_ptr, *gf_ptr;
    cudaGetSymbolAddress((void**)&gi_ptr, g_gi);
    cudaGetSymbolAddress((void**)&gf_ptr, g_gf);

    // gi = feat1 @ W_ih^T + b_ih : M=8192, N=1536, K=2048  (tf32 tensor path)
    {
        dim3 grid((3 * Hh) / 128, MROWS / 128);   // (12, 64)
        tf32_gemm_bias_kernel<<<grid, 256>>>(feat1, W_ih, b_ih, gi_ptr,
                                             MROWS, 3 * Hh, INPS);
    }
    // gf = feat0 @ W_fh^T + b_fh : M=8192, N=1024, K=1536  (tf32 tensor path)
    {
        dim3 grid((2 * Hh) / 128, MROWS / 128);   // (8, 64)
        tf32_gemm_bias_kernel<<<grid, 256>>>(feat0, W_fh, b_fh, gf_ptr,
                                             MROWS, 2 * Hh, FS);
    }
    // Recurrence: single persistent kernel, tensor-core gh, 64 steps internally
    {
        const int smem_bytes = (BBB * HS + BBB * GHS) * (int)sizeof(float); // 72448
        cudaFuncSetAttribute(gru_persistent_kernel,
                             cudaFuncAttributeMaxDynamicSharedMemorySize, smem_bytes);
        dim3 grid(Hh / NC, Bb / BBB);   // (32, 4) = 128 CTAs
        gru_persistent_kernel<<<grid, STEP_THREADS, smem_bytes>>>(
            gi_ptr, gf_ptr, W_hh, b_hh, out);
    }
}

// round 11
// speedup vs baseline: 1.5441x; 1.0054x over previous
#include <cuda_runtime.h>
#include <cuda_bf16.h>
#include <cstddef>

// Problem constants
#define Hh   512
#define INPS 2048
#define FS   1536
#define Bb   128
#define Tt   64
#define MROWS (Bb * Tt)          // 8192

// Persistent-recurrence tiling
#define NC   16                  // hidden cols per CTA (48 gate-cols)
#define BBB  32                  // batch rows per CTA
#define NBLK 128                 // total CTAs (32 col-chunks x 4 batch-chunks)
#define STEP_THREADS 256
#define HS   516                 // h_sm row stride (conflict-free frag LDS)
#define GHS  50                  // gh_sm row stride (48 + 2 pad)

// Scratch for precomputed projections (device statics: allocation-free)
__device__ float g_gi[(size_t)MROWS * (3 * Hh)];   // [B*T, 1536]
__device__ float g_gf[(size_t)MROWS * (2 * Hh)];   // [B*T, 1024]
__device__ unsigned int g_bar;                      // grid-barrier counter (monotone)

__device__ __forceinline__ unsigned int f2tf32(float x) {
    unsigned int u;
    asm("cvt.rna.tf32.f32 %0, %1;" : "=r"(u) : "f"(x));
    return u;
}

// ---------------------------------------------------------------------------
// Dual TF32 GEMM with 3-stage cp.async pipeline.
//   C[M,N] = A[M,K] * W[N,K]^T + bias[N]
// Blocks [0,768):   GEMM1  M=8192 N=1536 K=2048
// Blocks [768,1280): GEMM2 M=8192 N=1024 K=1536
// CTA tile 128x128, BK=32, 8 warps (2x4), warp tile 64x32 = 4x4 m16n8k8.
// fp32 lands in smem via cp.async; cvt.rna to tf32 on the fragment path
// (numerically identical to staging-side cvt).
// ---------------------------------------------------------------------------
#define GSTRIDE 36                       // 32 + 4 pad (fp32 words per row)
#define TILE_W  (128 * GSTRIDE)          // words per (matrix, stage)
#define STAGE_W (2 * TILE_W)             // A + W per stage
#define NSTAGE  3

__global__ __launch_bounds__(256, 2)
void tf32_gemm_dual_kernel(const float* __restrict__ A1, const float* __restrict__ W1,
                           const float* __restrict__ bias1, float* __restrict__ C1,
                           const float* __restrict__ A2, const float* __restrict__ W2,
                           const float* __restrict__ bias2, float* __restrict__ C2)
{
    extern __shared__ float smf[];       // [NSTAGE][2][128][GSTRIDE]

    const int bid = blockIdx.x;
    const float *A, *W, *bias;
    float* C;
    int N, K, bm, bn;
    if (bid < 768) {
        A = A1; W = W1; bias = bias1; C = C1;
        N = 3 * Hh; K = INPS;
        bn = bid % 12; bm = bid / 12;
    } else {
        const int b2 = bid - 768;
        A = A2; W = W2; bias = bias2; C = C2;
        N = 2 * Hh; K = FS;
        bn = b2 % 8; bm = b2 / 8;
    }

    const int tid  = threadIdx.x;
    const int lane = tid & 31;
    const int warp = tid >> 5;          // 0..7
    const int gid  = lane >> 2;         // 0..7
    const int tig  = lane & 3;          // 0..3
    const int wm   = warp >> 2;         // 0..1 -> M offset wm*64
    const int wn   = warp & 3;          // 0..3 -> N offset wn*32

    const float* Ablk = A + (size_t)bm * 128 * K;
    const float* Wblk = W + (size_t)bn * 128 * K;

    const unsigned int smem_base =
        (unsigned int)__cvta_generic_to_shared(smf);

    // Staging map: idx = tid + i*256 (i<4); row = idx>>3 (0..127), c4 = idx&7
    const int srow = tid >> 3;           // rows handled: srow + 32*i
    const int sc4  = tid & 7;

    float acc[4][4][4];
#pragma unroll
    for (int i = 0; i < 4; i++)
#pragma unroll
        for (int j = 0; j < 4; j++)
#pragma unroll
            for (int f = 0; f < 4; f++) acc[i][j][f] = 0.0f;

    const int KT = K >> 5;               // BK=32 tiles

    // Tile issue: cp.async 16B x (4 A + 4 W) per thread
    auto issue_tile = [&](int kt, int stage) {
        const int k0 = kt << 5;
        const unsigned int sA = smem_base + (stage * STAGE_W) * 4;
        const unsigned int sW = sA + TILE_W * 4;
#pragma unroll
        for (int i = 0; i < 4; i++) {
            const int row = srow + i * 32;
            const unsigned int off = (row * GSTRIDE + sc4 * 4) * 4;
            const float* ga = Ablk + (size_t)row * K + k0 + sc4 * 4;
            const float* gw = Wblk + (size_t)row * K + k0 + sc4 * 4;
            asm volatile("cp.async.ca.shared.global [%0], [%1], 16;\n"
                         :: "r"(sA + off), "l"(ga));
            asm volatile("cp.async.ca.shared.global [%0], [%1], 16;\n"
                         :: "r"(sW + off), "l"(gw));
        }
    };

    // Prologue: tiles 0 and 1 in flight
    issue_tile(0, 0);
    asm volatile("cp.async.commit_group;\n");
    issue_tile(1, 1);
    asm volatile("cp.async.commit_group;\n");

    for (int kt = 0; kt < KT; kt++) {
        asm volatile("cp.async.wait_group 1;\n");
        __syncthreads();                 // tile kt resident for all threads

        // Issue tile kt+2 into the stage consumed at iter kt-1 (safe: all
        // warps passed the barrier above after finishing that MMA).
        if (kt + 2 < KT)
            issue_tile(kt + 2, (kt + 2) % NSTAGE);
        asm volatile("cp.async.commit_group;\n");

        const float* Asb = smf + ((kt % NSTAGE) * STAGE_W);
        const float* Wsb = Asb + TILE_W;

#pragma unroll
        for (int kk = 0; kk < 32; kk += 8) {
            unsigned int af[4][4];
#pragma unroll
            for (int mt = 0; mt < 4; mt++) {
                const int r0 = wm * 64 + mt * 16 + gid;
                const float* p = &Asb[r0 * GSTRIDE + kk + tig];
                af[mt][0] = f2tf32(p[0]);
                af[mt][1] = f2tf32(p[8 * GSTRIDE]);
                af[mt][2] = f2tf32(p[4]);
                af[mt][3] = f2tf32(p[8 * GSTRIDE + 4]);
            }
            unsigned int bf[4][2];
#pragma unroll
            for (int nt = 0; nt < 4; nt++) {
                const int n0 = wn * 32 + nt * 8 + gid;
                const float* p = &Wsb[n0 * GSTRIDE + kk + tig];
                bf[nt][0] = f2tf32(p[0]);
                bf[nt][1] = f2tf32(p[4]);
            }
#pragma unroll
            for (int mt = 0; mt < 4; mt++)
#pragma unroll
                for (int nt = 0; nt < 4; nt++) {
                    asm volatile(
                        "mma.sync.aligned.m16n8k8.row.col.f32.tf32.tf32.f32 "
                        "{%0,%1,%2,%3}, {%4,%5,%6,%7}, {%8,%9}, {%0,%1,%2,%3};\n"
                        : "+f"(acc[mt][nt][0]), "+f"(acc[mt][nt][1]),
                          "+f"(acc[mt][nt][2]), "+f"(acc[mt][nt][3])
                        : "r"(af[mt][0]), "r"(af[mt][1]),
                          "r"(af[mt][2]), "r"(af[mt][3]),
                          "r"(bf[nt][0]), "r"(bf[nt][1]));
                }
        }
        __syncthreads();                 // done reading stage kt%3
    }

    // Epilogue: bias + store
#pragma unroll
    for (int mt = 0; mt < 4; mt++) {
        const int row = bm * 128 + wm * 64 + mt * 16 + gid;
#pragma unroll
        for (int nt = 0; nt < 4; nt++) {
            const int col = bn * 128 + wn * 32 + nt * 8 + tig * 2;
            const float b0 = bias[col], b1 = bias[col + 1];
            float2 v0 = make_float2(acc[mt][nt][0] + b0, acc[mt][nt][1] + b1);
            float2 v1 = make_float2(acc[mt][nt][2] + b0, acc[mt][nt][3] + b1);
            *(float2*)(C + (size_t)row * N + col)       = v0;
            *(float2*)(C + (size_t)(row + 8) * N + col) = v1;
        }
    }
}

// ---------------------------------------------------------------------------
// Persistent GRU recurrence with TENSOR-CORE gh GEMM (unchanged from R10).
// 128 CTAs, 1/SM, 256 threads. W_hh slice in registers as tf32 B-fragments
// (warps 0..5); h staged to smem as tf32; software grid barrier per step.
// ---------------------------------------------------------------------------
__global__ __launch_bounds__(STEP_THREADS, 1)
void gru_persistent_kernel(const float* __restrict__ gi,     // [B*T, 1536]
                           const float* __restrict__ gf,     // [B*T, 1024]
                           const float* __restrict__ W_hh,   // [1536, 512]
                           const float* __restrict__ b_hh,   // [1536]
                           float* __restrict__ out)          // eo [B,T,H] then hT [B,H]
{
    extern __shared__ unsigned int smu[];
    unsigned int* h_sm  = smu;                         // [32][HS] tf32 bits
    float*        gh_sm = (float*)(smu + BBB * HS);    // [32][GHS]

    const int tid  = threadIdx.x;
    const int lane = tid & 31;
    const int warp = tid >> 5;            // 0..7
    const int gid  = lane >> 2;           // 0..7
    const int tig  = lane & 3;            // 0..3
    const int c    = tid & (NC - 1);      // 0..15
    const int bg   = tid >> 4;            // 0..15
    const int colBase = blockIdx.x * NC;  // 0..496
    const int bBase   = blockIdx.y * BBB; // 0..96
    const int n = colBase + c;

    // ---- One-time: W_hh slice -> registers as tf32 B-fragments ----
    unsigned int wb0[64], wb1[64];
    if (warp < 6) {
        const float* Wg = W_hh +
            ((size_t)((warp >> 1) * Hh + colBase + (warp & 1) * 8 + gid)) * Hh;
#pragma unroll
        for (int ks = 0; ks < 64; ks++) {
            wb0[ks] = f2tf32(Wg[ks * 8 + tig]);
            wb1[ks] = f2tf32(Wg[ks * 8 + tig + 4]);
        }
    }

    const float bhr = b_hh[n];
    const float bhi = b_hh[Hh + n];
    const float bhn = b_hh[2 * Hh + n];

    for (int t = 0; t < Tt; t++) {
        // ---- Prefetch gate projections + hprev ----
        float gir[2][3], gfr[2][2], hpr[2];
#pragma unroll
        for (int j = 0; j < 2; j++) {
            const int b = bBase + bg * 2 + j;
            const size_t gib = ((size_t)b * Tt + t) * (3 * Hh);
            const size_t gfb = ((size_t)b * Tt + t) * (2 * Hh);
            gir[j][0] = gi[gib + n];
            gir[j][1] = gi[gib + Hh + n];
            gir[j][2] = gi[gib + 2 * Hh + n];
            gfr[j][0] = gf[gfb + n];
            gfr[j][1] = gf[gfb + Hh + n];
            hpr[j] = (t > 0) ? out[((size_t)b * Tt + (t - 1)) * Hh + n] : 0.0f;
        }

        // ---- Stage h_{t-1} into smem as tf32 ----
        if (t == 0) {
            uint4 z = make_uint4(0u, 0u, 0u, 0u);
            for (int i = tid; i < BBB * (Hh / 4); i += STEP_THREADS) {
                int bl = i >> 7;
                int kq = i & 127;
                *(uint4*)(h_sm + bl * HS + kq * 4) = z;
            }
        } else {
            for (int i = tid; i < BBB * (Hh / 4); i += STEP_THREADS) {
                int bl = i >> 7;
                int kq = i & 127;
                float4 v = *(const float4*)(out +
                    ((size_t)(bBase + bl) * Tt + (t - 1)) * Hh + kq * 4);
                uint4 u;
                u.x = f2tf32(v.x); u.y = f2tf32(v.y);
                u.z = f2tf32(v.z); u.w = f2tf32(v.w);
                *(uint4*)(h_sm + bl * HS + kq * 4) = u;
            }
        }
        __syncthreads();

        // ---- Tensor-core gh: [32,48] = h[32,512] @ Wslice[48,512]^T ----
        if (warp < 6) {
            float acc[2][4];
#pragma unroll
            for (int mt = 0; mt < 2; mt++)
#pragma unroll
                for (int f = 0; f < 4; f++) acc[mt][f] = 0.0f;

#pragma unroll
            for (int ks = 0; ks < 64; ks++) {
                const int kk = ks * 8;
#pragma unroll
                for (int mt = 0; mt < 2; mt++) {
                    const unsigned int* p = h_sm + (mt * 16 + gid) * HS + kk + tig;
                    unsigned int a0 = p[0];
                    unsigned int a1 = p[8 * HS];
                    unsigned int a2 = p[4];
                    unsigned int a3 = p[8 * HS + 4];
                    asm volatile(
                        "mma.sync.aligned.m16n8k8.row.col.f32.tf32.tf32.f32 "
                        "{%0,%1,%2,%3}, {%4,%5,%6,%7}, {%8,%9}, {%0,%1,%2,%3};\n"
                        : "+f"(acc[mt][0]), "+f"(acc[mt][1]),
                          "+f"(acc[mt][2]), "+f"(acc[mt][3])
                        : "r"(a0), "r"(a1), "r"(a2), "r"(a3),
                          "r"(wb0[ks]), "r"(wb1[ks]));
                }
            }
#pragma unroll
            for (int mt = 0; mt < 2; mt++) {
                int r = mt * 16 + gid;
                *(float2*)(gh_sm + (size_t)r * GHS + warp * 8 + tig * 2) =
                    make_float2(acc[mt][0], acc[mt][1]);
                *(float2*)(gh_sm + (size_t)(r + 8) * GHS + warp * 8 + tig * 2) =
                    make_float2(acc[mt][2], acc[mt][3]);
            }
        }
        __syncthreads();

        // ---- Gates + state update ----
#pragma unroll
        for (int j = 0; j < 2; j++) {
            const int bl = bg * 2 + j;
            const int b  = bBase + bl;

            float ghr = gh_sm[(size_t)bl * GHS + c]            + bhr;
            float ghi = gh_sm[(size_t)bl * GHS + NC + c]       + bhi;
            float ghn = gh_sm[(size_t)bl * GHS + 2 * NC + c]   + bhn;

            float xr = gir[j][0] + ghr + gfr[j][0];
            float xi = gir[j][1] + ghi + gfr[j][1];
            float resetgate = 1.0f / (1.0f + expf(-xr));
            float inputgate = 1.0f / (1.0f + expf(-xi));
            float newgate   = tanhf(gir[j][2] + resetgate * ghn);

            float hy = newgate + inputgate * (hpr[j] - newgate);

            out[((size_t)b * Tt + t) * Hh + n] = hy;
            if (t == Tt - 1)
                out[(size_t)Bb * Tt * Hh + (size_t)b * Hh + n] = hy;
        }

        // ---- Grid-wide barrier (all 128 CTAs co-resident) ----
        __threadfence();
        __syncthreads();
        if (tid == 0) {
            unsigned int old  = atomicAdd(&g_bar, 1u);
            unsigned int need = (old / NBLK + 1u) * NBLK;
            while (true) {
                unsigned int cur;
                asm volatile("ld.acquire.gpu.u32 %0, [%1];"
                             : "=r"(cur) : "l"(&g_bar));
                if (cur >= need) break;
            }
            __threadfence();
        }
        __syncthreads();
    }
}

// ---------------------------------------------------------------------------
// Launch
// ---------------------------------------------------------------------------
extern "C" void kernel_launch(void* const* d_in, const int* in_sizes, int n_in,
                              void* d_out, int out_size)
{
    const float* feat0 = (const float*)d_in[0];   // [B,T,FS]
    const float* feat1 = (const float*)d_in[1];   // [B,T,IN]
    const float* W_ih  = (const float*)d_in[2];   // [3H, IN]
    const float* b_ih  = (const float*)d_in[3];   // [3H]
    const float* W_hh  = (const float*)d_in[4];   // [3H, H]
    const float* b_hh  = (const float*)d_in[5];   // [3H]
    const float* W_fh  = (const float*)d_in[6];   // [2H, FS]
    const float* b_fh  = (const float*)d_in[7];   // [2H]
    float* out = (float*)d_out;

    float *gi_ptr, *gf_ptr;
    cudaGetSymbolAddress((void**)&gi_ptr, g_gi);
    cudaGetSymbolAddress((void**)&gf_ptr, g_gf);

    // Both projection GEMMs in ONE fused launch (tf32 + cp.async pipeline)
    {
        const int smem_bytes = NSTAGE * STAGE_W * (int)sizeof(float); // 110592
        cudaFuncSetAttribute(tf32_gemm_dual_kernel,
                             cudaFuncAttributeMaxDynamicSharedMemorySize, smem_bytes);
        tf32_gemm_dual_kernel<<<1280, 256, smem_bytes>>>(
            feat1, W_ih, b_ih, gi_ptr,
            feat0, W_fh, b_fh, gf_ptr);
    }
    // Recurrence: single persistent kernel, tensor-core gh, 64 steps internally
    {
        const int smem_bytes = (BBB * HS + BBB * GHS) * (int)sizeof(float); // 72448
        cudaFuncSetAttribute(gru_persistent_kernel,
                             cudaFuncAttributeMaxDynamicSharedMemorySize, smem_bytes);
        dim3 grid(Hh / NC, Bb / BBB);   // (32, 4) = 128 CTAs
        gru_persistent_kernel<<<grid, STEP_THREADS, smem_bytes>>>(
            gi_ptr, gf_ptr, W_hh, b_hh, out);
    }
}

// round 12
// speedup vs baseline: 1.6291x; 1.0550x over previous
#include <cuda_runtime.h>
#include <cuda_bf16.h>
#include <cstddef>

// Problem constants
#define Hh   512
#define INPS 2048
#define FS   1536
#define Bb   128
#define Tt   64
#define MROWS (Bb * Tt)          // 8192

// Persistent-recurrence tiling
#define NC   16                  // hidden cols per CTA (48 gate-cols)
#define BBB  32                  // batch rows per CTA
#define STEP_THREADS 256
#define HS   516                 // h_sm row stride (conflict-free frag LDS)
#define GHS  50                  // gh_sm row stride (48 + 2 pad)

// Scratch (device statics: allocation-free)
__device__ float g_gi[(size_t)MROWS * (3 * Hh)];       // [B*T, 1536]
__device__ float g_gf[(size_t)MROWS * (2 * Hh)];       // [B*T, 1024]
__device__ unsigned int g_hbuf[2][Bb][Hh];             // tf32 h, double-buffered
__device__ unsigned int g_barg[4];                     // per-batch-group barrier counters

__device__ __forceinline__ unsigned int f2tf32(float x) {
    unsigned int u;
    asm("cvt.rna.tf32.f32 %0, %1;" : "=r"(u) : "f"(x));
    return u;
}

// ---------------------------------------------------------------------------
// Dual TF32 GEMM with 3-stage cp.async pipeline (unchanged from R11).
// Blocks [0,768):   GEMM1  M=8192 N=1536 K=2048
// Blocks [768,1280): GEMM2 M=8192 N=1024 K=1536
// ---------------------------------------------------------------------------
#define GSTRIDE 36                       // 32 + 4 pad (fp32 words per row)
#define TILE_W  (128 * GSTRIDE)
#define STAGE_W (2 * TILE_W)
#define NSTAGE  3

__global__ __launch_bounds__(256, 2)
void tf32_gemm_dual_kernel(const float* __restrict__ A1, const float* __restrict__ W1,
                           const float* __restrict__ bias1, float* __restrict__ C1,
                           const float* __restrict__ A2, const float* __restrict__ W2,
                           const float* __restrict__ bias2, float* __restrict__ C2)
{
    extern __shared__ float smf[];

    const int bid = blockIdx.x;
    const float *A, *W, *bias;
    float* C;
    int N, K, bm, bn;
    if (bid < 768) {
        A = A1; W = W1; bias = bias1; C = C1;
        N = 3 * Hh; K = INPS;
        bn = bid % 12; bm = bid / 12;
    } else {
        const int b2 = bid - 768;
        A = A2; W = W2; bias = bias2; C = C2;
        N = 2 * Hh; K = FS;
        bn = b2 % 8; bm = b2 / 8;
    }

    const int tid  = threadIdx.x;
    const int lane = tid & 31;
    const int warp = tid >> 5;
    const int gid  = lane >> 2;
    const int tig  = lane & 3;
    const int wm   = warp >> 2;
    const int wn   = warp & 3;

    const float* Ablk = A + (size_t)bm * 128 * K;
    const float* Wblk = W + (size_t)bn * 128 * K;

    const unsigned int smem_base =
        (unsigned int)__cvta_generic_to_shared(smf);

    const int srow = tid >> 3;
    const int sc4  = tid & 7;

    float acc[4][4][4];
#pragma unroll
    for (int i = 0; i < 4; i++)
#pragma unroll
        for (int j = 0; j < 4; j++)
#pragma unroll
            for (int f = 0; f < 4; f++) acc[i][j][f] = 0.0f;

    const int KT = K >> 5;

    auto issue_tile = [&](int kt, int stage) {
        const int k0 = kt << 5;
        const unsigned int sA = smem_base + (stage * STAGE_W) * 4;
        const unsigned int sW = sA + TILE_W * 4;
#pragma unroll
        for (int i = 0; i < 4; i++) {
            const int row = srow + i * 32;
            const unsigned int off = (row * GSTRIDE + sc4 * 4) * 4;
            const float* ga = Ablk + (size_t)row * K + k0 + sc4 * 4;
            const float* gw = Wblk + (size_t)row * K + k0 + sc4 * 4;
            asm volatile("cp.async.ca.shared.global [%0], [%1], 16;\n"
                         :: "r"(sA + off), "l"(ga));
            asm volatile("cp.async.ca.shared.global [%0], [%1], 16;\n"
                         :: "r"(sW + off), "l"(gw));
        }
    };

    issue_tile(0, 0);
    asm volatile("cp.async.commit_group;\n");
    issue_tile(1, 1);
    asm volatile("cp.async.commit_group;\n");

    for (int kt = 0; kt < KT; kt++) {
        asm volatile("cp.async.wait_group 1;\n");
        __syncthreads();

        if (kt + 2 < KT)
            issue_tile(kt + 2, (kt + 2) % NSTAGE);
        asm volatile("cp.async.commit_group;\n");

        const float* Asb = smf + ((kt % NSTAGE) * STAGE_W);
        const float* Wsb = Asb + TILE_W;

#pragma unroll
        for (int kk = 0; kk < 32; kk += 8) {
            unsigned int af[4][4];
#pragma unroll
            for (int mt = 0; mt < 4; mt++) {
                const int r0 = wm * 64 + mt * 16 + gid;
                const float* p = &Asb[r0 * GSTRIDE + kk + tig];
                af[mt][0] = f2tf32(p[0]);
                af[mt][1] = f2tf32(p[8 * GSTRIDE]);
                af[mt][2] = f2tf32(p[4]);
                af[mt][3] = f2tf32(p[8 * GSTRIDE + 4]);
            }
            unsigned int bf[4][2];
#pragma unroll
            for (int nt = 0; nt < 4; nt++) {
                const int n0 = wn * 32 + nt * 8 + gid;
                const float* p = &Wsb[n0 * GSTRIDE + kk + tig];
                bf[nt][0] = f2tf32(p[0]);
                bf[nt][1] = f2tf32(p[4]);
            }
#pragma unroll
            for (int mt = 0; mt < 4; mt++)
#pragma unroll
                for (int nt = 0; nt < 4; nt++) {
                    asm volatile(
                        "mma.sync.aligned.m16n8k8.row.col.f32.tf32.tf32.f32 "
                        "{%0,%1,%2,%3}, {%4,%5,%6,%7}, {%8,%9}, {%0,%1,%2,%3};\n"
                        : "+f"(acc[mt][nt][0]), "+f"(acc[mt][nt][1]),
                          "+f"(acc[mt][nt][2]), "+f"(acc[mt][nt][3])
                        : "r"(af[mt][0]), "r"(af[mt][1]),
                          "r"(af[mt][2]), "r"(af[mt][3]),
                          "r"(bf[nt][0]), "r"(bf[nt][1]));
                }
        }
        __syncthreads();
    }

#pragma unroll
    for (int mt = 0; mt < 4; mt++) {
        const int row = bm * 128 + wm * 64 + mt * 16 + gid;
#pragma unroll
        for (int nt = 0; nt < 4; nt++) {
            const int col = bn * 128 + wn * 32 + nt * 8 + tig * 2;
            const float b0 = bias[col], b1 = bias[col + 1];
            float2 v0 = make_float2(acc[mt][nt][0] + b0, acc[mt][nt][1] + b1);
            float2 v1 = make_float2(acc[mt][nt][2] + b0, acc[mt][nt][3] + b1);
            *(float2*)(C + (size_t)row * N + col)       = v0;
            *(float2*)(C + (size_t)(row + 8) * N + col) = v1;
        }
    }
}

// ---------------------------------------------------------------------------
// Persistent GRU recurrence, latency-optimized:
//  - 4 independent 32-CTA group barriers (one per batch group)
//  - h exchanged via tf32 double-buffered scratch (producer-converted)
//  - hprev carried in registers; next-step gate LDGs issued before barrier
//  - MMA: 2 k-half accumulator sets (4 independent dependency chains)
// ---------------------------------------------------------------------------
__global__ __launch_bounds__(STEP_THREADS, 1)
void gru_persistent_kernel(const float* __restrict__ gi,     // [B*T, 1536]
                           const float* __restrict__ gf,     // [B*T, 1024]
                           const float* __restrict__ W_hh,   // [1536, 512]
                           const float* __restrict__ b_hh,   // [1536]
                           float* __restrict__ out)          // eo [B,T,H] then hT [B,H]
{
    extern __shared__ unsigned int smu[];
    unsigned int* h_sm  = smu;                         // [32][HS] tf32 bits
    float*        gh_sm = (float*)(smu + BBB * HS);    // [32][GHS]

    const int tid  = threadIdx.x;
    const int lane = tid & 31;
    const int warp = tid >> 5;            // 0..7
    const int gid  = lane >> 2;           // 0..7
    const int tig  = lane & 3;            // 0..3
    const int c    = tid & (NC - 1);      // 0..15
    const int bg   = tid >> 4;            // 0..15
    const int colBase = blockIdx.x * NC;  // 0..496
    const int grp     = blockIdx.y;       // batch group 0..3
    const int bBase   = grp * BBB;        // 0..96
    const int n = colBase + c;

    // ---- One-time: W_hh slice -> registers as tf32 B-fragments ----
    unsigned int wb0[64], wb1[64];
    if (warp < 6) {
        const float* Wg = W_hh +
            ((size_t)((warp >> 1) * Hh + colBase + (warp & 1) * 8 + gid)) * Hh;
#pragma unroll
        for (int ks = 0; ks < 64; ks++) {
            wb0[ks] = f2tf32(Wg[ks * 8 + tig]);
            wb1[ks] = f2tf32(Wg[ks * 8 + tig + 4]);
        }
    }

    const float bhr = b_hh[n];
    const float bhi = b_hh[Hh + n];
    const float bhn = b_hh[2 * Hh + n];

    const int b0 = bBase + bg * 2;        // this thread's two batch rows
    const int b1 = b0 + 1;

    // ---- Prefetch gates for t=0; hprev starts at 0 ----
    float gir[2][3], gfr[2][2];
    float hpr[2] = {0.0f, 0.0f};
    {
        const size_t gib0 = ((size_t)b0 * Tt) * (3 * Hh);
        const size_t gfb0 = ((size_t)b0 * Tt) * (2 * Hh);
        const size_t gib1 = ((size_t)b1 * Tt) * (3 * Hh);
        const size_t gfb1 = ((size_t)b1 * Tt) * (2 * Hh);
        gir[0][0] = gi[gib0 + n];          gir[1][0] = gi[gib1 + n];
        gir[0][1] = gi[gib0 + Hh + n];     gir[1][1] = gi[gib1 + Hh + n];
        gir[0][2] = gi[gib0 + 2 * Hh + n]; gir[1][2] = gi[gib1 + 2 * Hh + n];
        gfr[0][0] = gf[gfb0 + n];          gfr[1][0] = gf[gfb1 + n];
        gfr[0][1] = gf[gfb0 + Hh + n];     gfr[1][1] = gf[gfb1 + Hh + n];
    }

    for (int t = 0; t < Tt; t++) {
        // ---- Stage h_{t-1} (tf32 bits) into smem ----
        if (t == 0) {
            uint4 z = make_uint4(0u, 0u, 0u, 0u);
#pragma unroll
            for (int i = 0; i < 16; i++) {
                int idx = tid + i * STEP_THREADS;
                int bl = idx >> 7;
                int kq = idx & 127;
                *(uint4*)(h_sm + bl * HS + kq * 4) = z;
            }
        } else {
            const unsigned int* src = &g_hbuf[(t & 1) ^ 1][bBase][0];
#pragma unroll
            for (int i = 0; i < 16; i++) {
                int idx = tid + i * STEP_THREADS;
                int bl = idx >> 7;
                int kq = idx & 127;
                uint4 v = *(const uint4*)(src + (size_t)bl * Hh + kq * 4);
                *(uint4*)(h_sm + bl * HS + kq * 4) = v;
            }
        }
        __syncthreads();

        // ---- Tensor-core gh: [32,48] = h[32,512] @ Wslice[48,512]^T ----
        if (warp < 6) {
            float acc[2][2][4];                // [khalf][mt][frag]
#pragma unroll
            for (int kh = 0; kh < 2; kh++)
#pragma unroll
                for (int mt = 0; mt < 2; mt++)
#pragma unroll
                    for (int f = 0; f < 4; f++) acc[kh][mt][f] = 0.0f;

#pragma unroll
            for (int ks2 = 0; ks2 < 32; ks2++) {
#pragma unroll
                for (int kh = 0; kh < 2; kh++) {
                    const int ks = kh * 32 + ks2;
                    const int kk = ks * 8;
#pragma unroll
                    for (int mt = 0; mt < 2; mt++) {
                        const unsigned int* p = h_sm + (mt * 16 + gid) * HS + kk + tig;
                        unsigned int a0 = p[0];
                        unsigned int a1 = p[8 * HS];
                        unsigned int a2 = p[4];
                        unsigned int a3 = p[8 * HS + 4];
                        asm volatile(
                            "mma.sync.aligned.m16n8k8.row.col.f32.tf32.tf32.f32 "
                            "{%0,%1,%2,%3}, {%4,%5,%6,%7}, {%8,%9}, {%0,%1,%2,%3};\n"
                            : "+f"(acc[kh][mt][0]), "+f"(acc[kh][mt][1]),
                              "+f"(acc[kh][mt][2]), "+f"(acc[kh][mt][3])
                            : "r"(a0), "r"(a1), "r"(a2), "r"(a3),
                              "r"(wb0[ks]), "r"(wb1[ks]));
                    }
                }
            }
#pragma unroll
            for (int mt = 0; mt < 2; mt++) {
                int r = mt * 16 + gid;
                *(float2*)(gh_sm + (size_t)r * GHS + warp * 8 + tig * 2) =
                    make_float2(acc[0][mt][0] + acc[1][mt][0],
                                acc[0][mt][1] + acc[1][mt][1]);
                *(float2*)(gh_sm + (size_t)(r + 8) * GHS + warp * 8 + tig * 2) =
                    make_float2(acc[0][mt][2] + acc[1][mt][2],
                                acc[0][mt][3] + acc[1][mt][3]);
            }
        }
        __syncthreads();

        // ---- Gates + state update (all 256 threads) ----
#pragma unroll
        for (int j = 0; j < 2; j++) {
            const int bl = bg * 2 + j;
            const int b  = bBase + bl;

            float ghr = gh_sm[(size_t)bl * GHS + c]          + bhr;
            float ghi = gh_sm[(size_t)bl * GHS + NC + c]     + bhi;
            float ghn = gh_sm[(size_t)bl * GHS + 2 * NC + c] + bhn;

            float xr = gir[j][0] + ghr + gfr[j][0];
            float xi = gir[j][1] + ghi + gfr[j][1];
            float resetgate = 1.0f / (1.0f + expf(-xr));
            float inputgate = 1.0f / (1.0f + expf(-xi));
            float newgate   = tanhf(gir[j][2] + resetgate * ghn);

            float hy = newgate + inputgate * (hpr[j] - newgate);
            hpr[j] = hy;

            out[((size_t)b * Tt + t) * Hh + n] = hy;
            g_hbuf[t & 1][b][n] = f2tf32(hy);
            if (t == Tt - 1)
                out[(size_t)Bb * Tt * Hh + (size_t)b * Hh + n] = hy;
        }

        // ---- Prefetch next step's gates (hidden under barrier spin) ----
        if (t + 1 < Tt) {
            const size_t gib0 = ((size_t)b0 * Tt + t + 1) * (3 * Hh);
            const size_t gfb0 = ((size_t)b0 * Tt + t + 1) * (2 * Hh);
            const size_t gib1 = ((size_t)b1 * Tt + t + 1) * (3 * Hh);
            const size_t gfb1 = ((size_t)b1 * Tt + t + 1) * (2 * Hh);
            gir[0][0] = gi[gib0 + n];          gir[1][0] = gi[gib1 + n];
            gir[0][1] = gi[gib0 + Hh + n];     gir[1][1] = gi[gib1 + Hh + n];
            gir[0][2] = gi[gib0 + 2 * Hh + n]; gir[1][2] = gi[gib1 + 2 * Hh + n];
            gfr[0][0] = gf[gfb0 + n];          gfr[1][0] = gf[gfb1 + n];
            gfr[0][1] = gf[gfb0 + Hh + n];     gfr[1][1] = gf[gfb1 + Hh + n];
        }

        // ---- Group barrier: only the 32 CTAs sharing this batch group ----
        __threadfence();
        __syncthreads();
        if (tid == 0) {
            unsigned int old  = atomicAdd(&g_barg[grp], 1u);
            unsigned int need = (old / 32u + 1u) * 32u;
            while (true) {
                unsigned int cur;
                asm volatile("ld.acquire.gpu.u32 %0, [%1];"
                             : "=r"(cur) : "l"(&g_barg[grp]));
                if (cur >= need) break;
            }
            __threadfence();
        }
        __syncthreads();
    }
}

// ---------------------------------------------------------------------------
// Launch
// ---------------------------------------------------------------------------
extern "C" void kernel_launch(void* const* d_in, const int* in_sizes, int n_in,
                              void* d_out, int out_size)
{
    const float* feat0 = (const float*)d_in[0];   // [B,T,FS]
    const float* feat1 = (const float*)d_in[1];   // [B,T,IN]
    const float* W_ih  = (const float*)d_in[2];   // [3H, IN]
    const float* b_ih  = (const float*)d_in[3];   // [3H]
    const float* W_hh  = (const float*)d_in[4];   // [3H, H]
    const float* b_hh  = (const float*)d_in[5];   // [3H]
    const float* W_fh  = (const float*)d_in[6];   // [2H, FS]
    const float* b_fh  = (const float*)d_in[7];   // [2H]
    float* out = (float*)d_out;

    float *gi_ptr, *gf_ptr;
    cudaGetSymbolAddress((void**)&gi_ptr, g_gi);
    cudaGetSymbolAddress((void**)&gf_ptr, g_gf);

    // Both projection GEMMs in ONE fused launch (tf32 + cp.async pipeline)
    {
        const int smem_bytes = NSTAGE * STAGE_W * (int)sizeof(float); // 110592
        cudaFuncSetAttribute(tf32_gemm_dual_kernel,
                             cudaFuncAttributeMaxDynamicSharedMemorySize, smem_bytes);
        tf32_gemm_dual_kernel<<<1280, 256, smem_bytes>>>(
            feat1, W_ih, b_ih, gi_ptr,
            feat0, W_fh, b_fh, gf_ptr);
    }
    // Recurrence: single persistent kernel, tensor-core gh, 64 steps internally
    {
        const int smem_bytes = (BBB * HS + BBB * GHS) * (int)sizeof(float); // 72448
        cudaFuncSetAttribute(gru_persistent_kernel,
                             cudaFuncAttributeMaxDynamicSharedMemorySize, smem_bytes);
        dim3 grid(Hh / NC, Bb / BBB);   // (32, 4) = 128 CTAs
        gru_persistent_kernel<<<grid, STEP_THREADS, smem_bytes>>>(
            gi_ptr, gf_ptr, W_hh, b_hh, out);
    }
}